// round 7
// baseline (speedup 1.0000x reference)
#include <cuda_runtime.h>

// Langevin_2439541424651 — 131072 independent 200-step scalar recurrences.
// HBM-bound: ~100MB read + ~301MB write. R5 showed DRAM=66.7% with all pipes
// idle = latency-bound at regs=32. Fix: explicit 20-wide noise-load batching
// into a register array (guaranteed 20 LDGs in flight/warp ≈ 69KB/SM) with a
// 72-reg budget via __launch_bounds__(128, 7).

#define N_PART 1024
#define DX     128
#define STEPS  200
#define KB     20                                  // 200 = 10 chunks of 20
#define ND     (N_PART * DX)                       // 131072 threads
#define TOT_XT ((long)N_PART * STEPS * DX)

__global__ void __launch_bounds__(128, 7) langevin_kernel(
    const float* __restrict__ x0,      // [N, DX]
    const float* __restrict__ y0,      // [N, DX]
    const float* __restrict__ mean,    // [DX]
    const float* __restrict__ var,     // [DX]
    const float* __restrict__ gammas,  // [STEPS]
    const float* __restrict__ noise,   // [STEPS, N, DX]
    float* __restrict__ x_tot,         // [N, STEPS, DX]
    float* __restrict__ y_tot,
    float* __restrict__ out,
    float* __restrict__ steps_out)     // [N, STEPS]
{
    __shared__ float s_g[STEPS];
    __shared__ float s_s[STEPS];

    for (int k = threadIdx.x; k < STEPS; k += blockDim.x) {
        float g = gammas[k];
        s_g[k] = g;
        s_s[k] = sqrtf(2.0f * g);
    }

    int tid = blockIdx.x * blockDim.x + threadIdx.x;   // 0 .. ND-1

    // Steps tensor [N, STEPS, 1]: coalesced prologue, no tail kernel.
    for (int i = tid; i < N_PART * STEPS; i += ND)
        steps_out[i] = (float)(i % STEPS);

    __syncthreads();

    int d = tid & (DX - 1);
    int n = tid >> 7;

    float x  = x0[tid];
    float yv = y0[tid];
    float m  = mean[d];
    float iv = 1.0f / var[d];

    long base = (long)n * STEPS * DX + d;
    const float* __restrict__ zp = noise + tid;

    // t_old = x - c*(x-m);  x_new = t_old + s*z
    // t_old - t_new = (t_old - x_new) + c*(x_new - m),  c = gamma/var
    for (int kb = 0; kb < STEPS; kb += KB) {
        float zbuf[KB];
#pragma unroll
        for (int j = 0; j < KB; ++j)
            zbuf[j] = zp[(long)(kb + j) * ND];

#pragma unroll
        for (int j = 0; j < KB; ++j) {
            int k = kb + j;
            float g = s_g[k];
            float s = s_s[k];

            float c     = g * iv;
            float t_old = fmaf(-c, x - m, x);
            float xn    = fmaf(s, zbuf[j], t_old);
            float diff  = fmaf(c, xn - m, t_old - xn);
            x = xn;

            long o = base + (long)k * DX;
            x_tot[o] = xn;
            y_tot[o] = yv;
            out[o]   = diff;
        }
    }
}

extern "C" void kernel_launch(void* const* d_in, const int* in_sizes, int n_in,
                              void* d_out, int out_size)
{
    const float* x0     = (const float*)d_in[0];
    const float* y0     = (const float*)d_in[1];
    const float* mean   = (const float*)d_in[2];
    const float* var    = (const float*)d_in[3];
    const float* gammas = (const float*)d_in[4];
    const float* noise  = (const float*)d_in[5];

    float* base  = (float*)d_out;
    float* x_tot = base;                 // [N, S, D]
    float* y_tot = base + TOT_XT;
    float* outp  = base + 2 * TOT_XT;
    float* steps = base + 3 * TOT_XT;    // [N, S, 1]

    langevin_kernel<<<ND / 128, 128>>>(x0, y0, mean, var, gammas, noise,
                                       x_tot, y_tot, outp, steps);
}

// round 8
// speedup vs baseline: 1.0637x; 1.0637x over previous
#include <cuda_runtime.h>

// Langevin_2439541424651 — 131072 independent 200-step recurrences, float2
// per thread (65536 threads). HBM-bound: ~100MB read + ~301MB write.
// Plain cached ld/st (.cs regresses hard on GB300: R3/R4). float2 halves
// memory-instruction count vs R5 at still-healthy occupancy (443 thr/SM).

#define N_PART 1024
#define DX     128
#define STEPS  200
#define ND2    (N_PART * DX / 2)                  // 65536 float2 work items
#define TOT_XT ((long)N_PART * STEPS * DX)

__global__ void __launch_bounds__(128) langevin_kernel(
    const float2* __restrict__ x0,      // [N*DX/2]
    const float2* __restrict__ y0,
    const float2* __restrict__ mean2,   // [DX/2]
    const float2* __restrict__ var2,    // [DX/2]
    const float*  __restrict__ gammas,  // [STEPS]
    const float2* __restrict__ noise,   // [STEPS * N * DX/2]
    float2* __restrict__ x_tot,         // [N, STEPS, DX/2]
    float2* __restrict__ y_tot,
    float2* __restrict__ out,
    float*  __restrict__ steps_out)     // [N, STEPS]
{
    __shared__ float s_g[STEPS];
    __shared__ float s_s[STEPS];

    for (int k = threadIdx.x; k < STEPS; k += blockDim.x) {
        float g = gammas[k];
        s_g[k] = g;
        s_s[k] = sqrtf(2.0f * g);
    }

    int tid = blockIdx.x * blockDim.x + threadIdx.x;   // 0 .. ND2-1

    // Steps tensor [N, STEPS, 1]: coalesced prologue, no tail kernel.
    for (int i = tid; i < N_PART * STEPS; i += ND2)
        steps_out[i] = (float)(i % STEPS);

    __syncthreads();

    int d2 = tid & 63;                  // 64 float2 per row
    int n  = tid >> 6;

    float2 x  = x0[tid];
    float2 yv = y0[tid];
    float2 m  = mean2[d2];
    float2 vv = var2[d2];
    float2 iv = make_float2(1.0f / vv.x, 1.0f / vv.y);

    long base = (long)n * STEPS * 64 + d2;             // in float2 units
    const float2* __restrict__ zp = noise + tid;

    // t_old = x - c*(x-m);  x_new = t_old + s*z
    // t_old - t_new = (t_old - x_new) + c*(x_new - m),  c = gamma/var
#pragma unroll 8
    for (int k = 0; k < STEPS; ++k) {
        float g = s_g[k];
        float s = s_s[k];
        float2 z = zp[(long)k * ND2];

        float2 xn, df;
        {
            float c = g * iv.x;
            float t = fmaf(-c, x.x - m.x, x.x);
            xn.x = fmaf(s, z.x, t);
            df.x = fmaf(c, xn.x - m.x, t - xn.x);
        }
        {
            float c = g * iv.y;
            float t = fmaf(-c, x.y - m.y, x.y);
            xn.y = fmaf(s, z.y, t);
            df.y = fmaf(c, xn.y - m.y, t - xn.y);
        }
        x = xn;

        long o = base + (long)k * 64;
        x_tot[o] = xn;
        y_tot[o] = yv;
        out[o]   = df;
    }
}

extern "C" void kernel_launch(void* const* d_in, const int* in_sizes, int n_in,
                              void* d_out, int out_size)
{
    const float* x0     = (const float*)d_in[0];
    const float* y0     = (const float*)d_in[1];
    const float* mean   = (const float*)d_in[2];
    const float* var    = (const float*)d_in[3];
    const float* gammas = (const float*)d_in[4];
    const float* noise  = (const float*)d_in[5];

    float* base  = (float*)d_out;
    float* x_tot = base;                 // [N, S, D]
    float* y_tot = base + TOT_XT;
    float* outp  = base + 2 * TOT_XT;
    float* steps = base + 3 * TOT_XT;    // [N, S, 1]

    langevin_kernel<<<ND2 / 128, 128>>>(
        (const float2*)x0, (const float2*)y0,
        (const float2*)mean, (const float2*)var,
        gammas, (const float2*)noise,
        (float2*)x_tot, (float2*)y_tot, (float2*)outp, steps);
}